// round 11
// baseline (speedup 1.0000x reference)
#include <cuda_runtime.h>
#include <math.h>

#define Bn 8
#define HW 4096
#define Mm 32768   // B*HW
#define HD 64

typedef unsigned long long u64;

// packed fp32x2 FMA: acc = a*b + acc (elementwise on two packed floats)
#define FFMA2(acc, a, b) \
    asm("fma.rn.f32x2 %0, %1, %2, %0;" : "+l"(acc) : "l"(a), "l"(b))

__device__ __forceinline__ u64 dup_f32(float v) {
    u64 r; asm("mov.b64 %0, {%1, %1};" : "=l"(r) : "f"(v)); return r;
}
__device__ __forceinline__ float2 u64_f2(u64 u) {
    float2 v; asm("mov.b64 {%0, %1}, %2;" : "=f"(v.x), "=f"(v.y) : "l"(u)); return v;
}

// Scratch (static device globals; no allocation allowed)
__device__ __align__(16) float g_qkv[9u * Mm * HD];   // [s*3+i][m][c]
__device__ __align__(16) float g_off[2][Mm * 18];     // offsets for dil 2,3
__device__ __align__(16) float g_defk[2][Mm * HD];    // deformed k
__device__ __align__(16) float g_defv[2][Mm * HD];    // deformed v
__device__ __align__(16) float g_attn[Mm * 192];      // attention outputs
__device__ __align__(16) float g_wT[2 * 9 * 64 * 64]; // transposed def weights

// ---------------------------------------------------------------------------
// Weight transpose: g_wT[dil][kk][o][c] = dw[o][c][kk].  One-time, tiny.
// ---------------------------------------------------------------------------
__global__ void wtrans_kernel(const float* __restrict__ dw2,
                              const float* __restrict__ dw3)
{
    int idx = blockIdx.x * 256 + threadIdx.x;      // 0 .. 73727
    if (idx >= 73728) return;
    int c  = idx & 63;
    int o  = (idx >> 6) & 63;
    int kk = (idx >> 12) % 9;
    int dil = idx / 36864;
    const float* dw = dil ? dw3 : dw2;
    g_wT[idx] = dw[o * 576 + c * 9 + kk];
}

// ---------------------------------------------------------------------------
// SGEMM: C[m,n] = sum_k A[m,k] * Bw[n,k]; 128x64 tile, 8x4 micro, k-chunk 16,
// double-buffered smem, FFMA2 packed over m-pairs.
// mode 0: scatter into g_qkv[(n/64)][m][n%64]   (qkv projection, N=576)
// mode 1: Cout[m*192+n] = acc + bias[n], A taken from g_attn (final proj)
// ---------------------------------------------------------------------------
__global__ __launch_bounds__(256) void sgemm_kernel(
    const float* __restrict__ A, const float* __restrict__ Bw,
    const float* __restrict__ bias, float* __restrict__ Cout, int mode)
{
    __shared__ __align__(16) float As[2][16][132];
    __shared__ __align__(16) float Bs[2][16][68];
    int tid = threadIdx.x;
    int tx = tid & 15, ty = tid >> 4;    // tx: 4 n's, ty: 8 m's (4 m-pairs)
    int m0 = blockIdx.x * 128, n0 = blockIdx.y * 64;
    const float* Ap = (mode == 0) ? A : g_attn;
    u64 acc2[4][4] = {};                 // [m-pair][n]

    int a_m0 = tid >> 2,        a_kq0 = tid & 3;
    int a_m1 = (tid + 256) >> 2, a_kq1 = (tid + 256) & 3;
    int b_n = tid >> 2, b_kq = tid & 3;

    // stage chunk 0
    {
        float4 av0 = *(const float4*)&Ap[(size_t)(m0 + a_m0) * 192 + a_kq0 * 4];
        float4 av1 = *(const float4*)&Ap[(size_t)(m0 + a_m1) * 192 + a_kq1 * 4];
        float4 bv  = *(const float4*)&Bw[(size_t)(n0 + b_n) * 192 + b_kq * 4];
        As[0][a_kq0 * 4 + 0][a_m0] = av0.x; As[0][a_kq0 * 4 + 1][a_m0] = av0.y;
        As[0][a_kq0 * 4 + 2][a_m0] = av0.z; As[0][a_kq0 * 4 + 3][a_m0] = av0.w;
        As[0][a_kq1 * 4 + 0][a_m1] = av1.x; As[0][a_kq1 * 4 + 1][a_m1] = av1.y;
        As[0][a_kq1 * 4 + 2][a_m1] = av1.z; As[0][a_kq1 * 4 + 3][a_m1] = av1.w;
        Bs[0][b_kq * 4 + 0][b_n] = bv.x; Bs[0][b_kq * 4 + 1][b_n] = bv.y;
        Bs[0][b_kq * 4 + 2][b_n] = bv.z; Bs[0][b_kq * 4 + 3][b_n] = bv.w;
    }
    __syncthreads();

    int cur = 0;
    for (int kc = 0; kc < 12; kc++) {
        float4 pa0, pa1, pb;
        if (kc < 11) {
            int k0n = (kc + 1) * 16;
            pa0 = *(const float4*)&Ap[(size_t)(m0 + a_m0) * 192 + k0n + a_kq0 * 4];
            pa1 = *(const float4*)&Ap[(size_t)(m0 + a_m1) * 192 + k0n + a_kq1 * 4];
            pb  = *(const float4*)&Bw[(size_t)(n0 + b_n) * 192 + k0n + b_kq * 4];
        }
        #pragma unroll
        for (int kk = 0; kk < 16; kk++) {
            ulonglong2 a01 = *(const ulonglong2*)&As[cur][kk][ty * 8];
            ulonglong2 a23 = *(const ulonglong2*)&As[cur][kk][ty * 8 + 4];
            float4 b  = *(const float4*)&Bs[cur][kk][tx * 4];
            u64 bd0 = dup_f32(b.x), bd1 = dup_f32(b.y);
            u64 bd2 = dup_f32(b.z), bd3 = dup_f32(b.w);
            FFMA2(acc2[0][0], a01.x, bd0); FFMA2(acc2[0][1], a01.x, bd1);
            FFMA2(acc2[0][2], a01.x, bd2); FFMA2(acc2[0][3], a01.x, bd3);
            FFMA2(acc2[1][0], a01.y, bd0); FFMA2(acc2[1][1], a01.y, bd1);
            FFMA2(acc2[1][2], a01.y, bd2); FFMA2(acc2[1][3], a01.y, bd3);
            FFMA2(acc2[2][0], a23.x, bd0); FFMA2(acc2[2][1], a23.x, bd1);
            FFMA2(acc2[2][2], a23.x, bd2); FFMA2(acc2[2][3], a23.x, bd3);
            FFMA2(acc2[3][0], a23.y, bd0); FFMA2(acc2[3][1], a23.y, bd1);
            FFMA2(acc2[3][2], a23.y, bd2); FFMA2(acc2[3][3], a23.y, bd3);
        }
        if (kc < 11) {
            int nxt = cur ^ 1;
            As[nxt][a_kq0 * 4 + 0][a_m0] = pa0.x; As[nxt][a_kq0 * 4 + 1][a_m0] = pa0.y;
            As[nxt][a_kq0 * 4 + 2][a_m0] = pa0.z; As[nxt][a_kq0 * 4 + 3][a_m0] = pa0.w;
            As[nxt][a_kq1 * 4 + 0][a_m1] = pa1.x; As[nxt][a_kq1 * 4 + 1][a_m1] = pa1.y;
            As[nxt][a_kq1 * 4 + 2][a_m1] = pa1.z; As[nxt][a_kq1 * 4 + 3][a_m1] = pa1.w;
            Bs[nxt][b_kq * 4 + 0][b_n] = pb.x; Bs[nxt][b_kq * 4 + 1][b_n] = pb.y;
            Bs[nxt][b_kq * 4 + 2][b_n] = pb.z; Bs[nxt][b_kq * 4 + 3][b_n] = pb.w;
        }
        __syncthreads();
        cur ^= 1;
    }

    // unpack: m = m0 + ty*8 + (2p + half)
    if (mode == 0) {
        size_t bufbase = (size_t)blockIdx.y * Mm * 64;
        #pragma unroll
        for (int p = 0; p < 4; p++) {
            float2 c0 = u64_f2(acc2[p][0]);
            float2 c1 = u64_f2(acc2[p][1]);
            float2 c2 = u64_f2(acc2[p][2]);
            float2 c3 = u64_f2(acc2[p][3]);
            int m = m0 + ty * 8 + p * 2;
            float4 lo = {c0.x, c1.x, c2.x, c3.x};
            float4 hi = {c0.y, c1.y, c2.y, c3.y};
            *(float4*)&g_qkv[bufbase + (size_t)m * 64 + tx * 4]       = lo;
            *(float4*)&g_qkv[bufbase + (size_t)(m + 1) * 64 + tx * 4] = hi;
        }
    } else {
        float4 b4 = *(const float4*)&bias[n0 + tx * 4];
        #pragma unroll
        for (int p = 0; p < 4; p++) {
            float2 c0 = u64_f2(acc2[p][0]);
            float2 c1 = u64_f2(acc2[p][1]);
            float2 c2 = u64_f2(acc2[p][2]);
            float2 c3 = u64_f2(acc2[p][3]);
            int m = m0 + ty * 8 + p * 2;
            float4 lo = {c0.x + b4.x, c1.x + b4.y, c2.x + b4.z, c3.x + b4.w};
            float4 hi = {c0.y + b4.x, c1.y + b4.y, c2.y + b4.z, c3.y + b4.w};
            *(float4*)&Cout[(size_t)m * 192 + n0 + tx * 4]       = lo;
            *(float4*)&Cout[(size_t)(m + 1) * 192 + n0 + tx * 4] = hi;
        }
    }
}

// ---------------------------------------------------------------------------
// Offset conv: dilated 3x3 conv on k branch, 64 -> 18 ch, zero pad = dil.
// blockIdx.y selects dil (2 or 3). Block: 32 px (8 warps x 4 px),
// lanes = (px_sub 4) x (channel-octet 8). FFMA2 packed over channel pairs.
// ---------------------------------------------------------------------------
__global__ __launch_bounds__(256) void offconv_kernel(
    const float* __restrict__ ow2, const float* __restrict__ ob2,
    const float* __restrict__ ow3, const float* __restrict__ ob3)
{
    __shared__ __align__(16) float ws[18 * 612];
    int dil_idx = blockIdx.y;
    int dil = dil_idx + 2;
    const float* ow = dil_idx ? ow3 : ow2;
    const float* ob = dil_idx ? ob3 : ob2;
    const float* kin = &g_qkv[(size_t)(4 + dil_idx) * Mm * HD];
    float* offout = g_off[dil_idx];
    int tid = threadIdx.x;

    for (int i = tid; i < 18 * 576; i += 256) {
        int oc = i / 576, r = i % 576, c = r / 9, kk = r % 9;
        ws[oc * 612 + kk * 68 + c] = ow[i];
    }
    __syncthreads();

    int wr = tid >> 5, lane = tid & 31;
    int pxs = lane >> 3, cq = lane & 7;
    int m = blockIdx.x * 32 + wr * 4 + pxs;
    int b = m >> 12, hw = m & 4095, h = hw >> 6, w = hw & 63;

    u64 acc2[18] = {};

    for (int kk = 0; kk < 9; kk++) {
        int y = h + (kk / 3 - 1) * dil;
        int x = w + (kk % 3 - 1) * dil;
        ulonglong2 k0 = {0, 0}, k1 = {0, 0};
        if ((unsigned)y < 64u && (unsigned)x < 64u) {
            const float* kp = kin + (size_t)((b << 12) + (y << 6) + x) * 64 + cq * 8;
            k0 = *(const ulonglong2*)kp;
            k1 = *(const ulonglong2*)(kp + 4);
        }
        const float* wsk = ws + kk * 68 + cq * 8;
        #pragma unroll
        for (int oc = 0; oc < 18; oc++) {
            ulonglong2 w0 = *(const ulonglong2*)(wsk + oc * 612);
            ulonglong2 w1 = *(const ulonglong2*)(wsk + oc * 612 + 4);
            FFMA2(acc2[oc], k0.x, w0.x);
            FFMA2(acc2[oc], k0.y, w0.y);
            FFMA2(acc2[oc], k1.x, w1.x);
            FFMA2(acc2[oc], k1.y, w1.y);
        }
    }
    #pragma unroll
    for (int oc = 0; oc < 18; oc++) {
        float2 f = u64_f2(acc2[oc]);
        float a = f.x + f.y;
        a += __shfl_xor_sync(0xffffffffu, a, 1);
        a += __shfl_xor_sync(0xffffffffu, a, 2);
        a += __shfl_xor_sync(0xffffffffu, a, 4);
        if (cq == 0) offout[(size_t)m * 18 + oc] = a + ob[oc];
    }
}

// ---------------------------------------------------------------------------
// Deformable conv for k AND v, tap-chunked + software-pipelined.
// GEMM layout: px = LANE (32 distinct smem rows per LDS.128, zero lane
// duplication, conflict-free), warp w owns outs {w, w+8, .., w+56}, both
// tensors per lane. Weight reads are single-wavefront broadcasts.
// ---------------------------------------------------------------------------
__global__ __launch_bounds__(256, 2) void deform_kernel(
    const float* __restrict__ db2, const float* __restrict__ db3)
{
    __shared__ __align__(16) float s_k[2][32][68];
    __shared__ __align__(16) float s_v[2][32][68];
    __shared__ __align__(16) float w_s[2][64][68];
    __shared__ __align__(16) int4   s_b4[288];   // [kk*32 + px]
    __shared__ __align__(16) float4 s_w4[288];

    int dil_idx = blockIdx.y;
    int dil = dil_idx + 2;
    const float* db = dil_idx ? db3 : db2;
    const float* kin = &g_qkv[(size_t)(4 + dil_idx) * Mm * HD];
    const float* vin = &g_qkv[(size_t)(7 + dil_idx) * Mm * HD];
    const float* off = g_off[dil_idx];
    float* kout = g_defk[dil_idx];
    float* vout = g_defv[dil_idx];

    int tid = threadIdx.x;
    int m0 = blockIdx.x * 32;
    int bpix = m0 & ~4095;      // batch base (block within one batch)

    // ---- corner precompute: all 9 taps x 32 px ----
    for (int i = tid; i < 288; i += 256) {
        int px = i & 31, kk = i >> 5;
        int m = m0 + px;
        int hw = m & 4095;
        int h = hw >> 6, w = hw & 63;
        float oy = off[(size_t)m * 18 + kk * 2 + 0];
        float ox = off[(size_t)m * 18 + kk * 2 + 1];
        float py  = (float)(h + (kk / 3 - 1) * dil) + oy;
        float pxf = (float)(w + (kk % 3 - 1) * dil) + ox;
        float y0f = floorf(py), x0f = floorf(pxf);
        float wy = py - y0f, wx = pxf - x0f;
        int y0 = (int)y0f, x0 = (int)x0f;
        int yv0 = ((unsigned)y0 < 64u), yv1 = ((unsigned)(y0 + 1) < 64u);
        int xv0 = ((unsigned)x0 < 64u), xv1 = ((unsigned)(x0 + 1) < 64u);
        int4 bs;
        bs.x = (yv0 && xv0) ? ((y0 << 6) + x0)           : -1;
        bs.y = (yv0 && xv1) ? ((y0 << 6) + x0 + 1)       : -1;
        bs.z = (yv1 && xv0) ? (((y0 + 1) << 6) + x0)     : -1;
        bs.w = (yv1 && xv1) ? (((y0 + 1) << 6) + x0 + 1) : -1;
        float4 wt;
        wt.x = (1.f - wy) * (1.f - wx);
        wt.y = (1.f - wy) * wx;
        wt.z = wy * (1.f - wx);
        wt.w = wy * wx;
        s_b4[kk * 32 + px] = bs;
        s_w4[kk * 32 + px] = wt;
    }
    __syncthreads();

    int warp = tid >> 5, lane = tid & 31;
    int slot = lane >> 4, cq = lane & 15;
    int tens = warp >= 4;
    const float* srcT = tens ? vin : kin;
    const float* rowbase = srcT + (size_t)bpix * 64 + cq * 4;
    const float* wbase = &g_wT[(size_t)dil_idx * 9 * 4096];
    int w_o = tid >> 4, w_q = tid & 15;     // weight-staging role

    float4 sm[4];       // sampled values in flight
    float4 wrg[4];      // weight values in flight

#define SAMPLE_TAP(KK)                                                        \
    do {                                                                      \
        _Pragma("unroll")                                                     \
        for (int it = 0; it < 4; it++) {                                      \
            int px = (warp * 8 + it * 2 + slot) & 31;                         \
            int4 bs = s_b4[(KK) * 32 + px];                                   \
            float4 wt = s_w4[(KK) * 32 + px];                                 \
            float4 a = {0.f, 0.f, 0.f, 0.f};                                  \
            if (bs.x >= 0) {                                                  \
                float4 v = *(const float4*)(rowbase + (size_t)bs.x * 64);     \
                a.x += wt.x * v.x; a.y += wt.x * v.y;                         \
                a.z += wt.x * v.z; a.w += wt.x * v.w;                         \
            }                                                                 \
            if (bs.y >= 0) {                                                  \
                float4 v = *(const float4*)(rowbase + (size_t)bs.y * 64);     \
                a.x += wt.y * v.x; a.y += wt.y * v.y;                         \
                a.z += wt.y * v.z; a.w += wt.y * v.w;                         \
            }                                                                 \
            if (bs.z >= 0) {                                                  \
                float4 v = *(const float4*)(rowbase + (size_t)bs.z * 64);     \
                a.x += wt.z * v.x; a.y += wt.z * v.y;                         \
                a.z += wt.z * v.z; a.w += wt.z * v.w;                         \
            }                                                                 \
            if (bs.w >= 0) {                                                  \
                float4 v = *(const float4*)(rowbase + (size_t)bs.w * 64);     \
                a.x += wt.w * v.x; a.y += wt.w * v.y;                         \
                a.z += wt.w * v.z; a.w += wt.w * v.w;                         \
            }                                                                 \
            sm[it] = a;                                                       \
        }                                                                     \
    } while (0)

#define STORE_TAP(BUF)                                                        \
    do {                                                                      \
        _Pragma("unroll")                                                     \
        for (int it = 0; it < 4; it++) {                                      \
            int px = (warp * 8 + it * 2 + slot) & 31;                         \
            float* dst = tens ? &s_v[BUF][px][0] : &s_k[BUF][px][0];          \
            *(float4*)&dst[cq * 4] = sm[it];                                  \
        }                                                                     \
    } while (0)

#define LOAD_W(KK)                                                            \
    do {                                                                      \
        const float* wsrc = wbase + (KK) * 4096;                              \
        _Pragma("unroll")                                                     \
        for (int i = 0; i < 4; i++)                                           \
            wrg[i] = *(const float4*)&wsrc[(w_o + i * 16) * 64 + w_q * 4];    \
    } while (0)

#define STORE_W(BUF)                                                          \
    do {                                                                      \
        _Pragma("unroll")                                                     \
        for (int i = 0; i < 4; i++)                                           \
            *(float4*)&w_s[BUF][w_o + i * 16][w_q * 4] = wrg[i];              \
    } while (0)

    u64 accK2[8] = {}, accV2[8] = {};

    // prologue: tap 0 into stage 0
    SAMPLE_TAP(0);
    LOAD_W(0);
    STORE_TAP(0);
    STORE_W(0);
    __syncthreads();

    for (int kk = 0; kk < 9; kk++) {
        int cur = kk & 1;
        if (kk < 8) {           // launch next tap's loads (hidden by GEMM)
            SAMPLE_TAP(kk + 1);
            LOAD_W(kk + 1);
        }
        // GEMM over 64 channels of tap kk: lane = px, warp owns 8 outs
        #pragma unroll
        for (int c = 0; c < 64; c += 4) {
            ulonglong2 kx = *(const ulonglong2*)&s_k[cur][lane][c];
            ulonglong2 vx = *(const ulonglong2*)&s_v[cur][lane][c];
            #pragma unroll
            for (int j = 0; j < 8; j++) {
                ulonglong2 wv = *(const ulonglong2*)&w_s[cur][warp + j * 8][c];
                FFMA2(accK2[j], kx.x, wv.x); FFMA2(accK2[j], kx.y, wv.y);
                FFMA2(accV2[j], vx.x, wv.x); FFMA2(accV2[j], vx.y, wv.y);
            }
        }
        if (kk < 8) {
            STORE_TAP(cur ^ 1);
            STORE_W(cur ^ 1);
        }
        __syncthreads();
    }

    // horizontal add + bias
    float accK[8], accV[8];
    #pragma unroll
    for (int j = 0; j < 8; j++) {
        float bv = db[warp + j * 8];
        float2 fk = u64_f2(accK2[j]);
        float2 fv = u64_f2(accV2[j]);
        accK[j] = fk.x + fk.y + bv;
        accV[j] = fv.x + fv.y + bv;
    }

    // ---- output: stage via smem (reuse s_k), coalesced STG.128 ----
    float* so = &s_k[0][0][0];    // [32][68]
    #pragma unroll
    for (int j = 0; j < 8; j++)
        so[lane * 68 + warp + j * 8] = accK[j];
    __syncthreads();
    for (int idx = tid; idx < 512; idx += 256) {
        int px = idx >> 4, q = idx & 15;
        float4 val = *(const float4*)&so[px * 68 + q * 4];
        *(float4*)&kout[(size_t)(m0 + px) * 64 + q * 4] = val;
    }
    __syncthreads();
    #pragma unroll
    for (int j = 0; j < 8; j++)
        so[lane * 68 + warp + j * 8] = accV[j];
    __syncthreads();
    for (int idx = tid; idx < 512; idx += 256) {
        int px = idx >> 4, q = idx & 15;
        float4 val = *(const float4*)&so[px * 68 + q * 4];
        *(float4*)&vout[(size_t)(m0 + px) * 64 + q * 4] = val;
    }
}

// ---------------------------------------------------------------------------
// Attention: warp per pixel, grid (4096, 3 dilations). 9-tap softmax.
// float2-vectorized channel loads. OOB taps contribute logit EXACTLY 0.
// ---------------------------------------------------------------------------
__global__ __launch_bounds__(256) void attn_kernel()
{
    int dil_idx = blockIdx.y;
    int dil = dil_idx + 1;
    int warp = threadIdx.x >> 5, lane = threadIdx.x & 31;
    int m = blockIdx.x * 8 + warp;
    int b = m >> 12, hw = m & 4095, h = hw >> 6, w = hw & 63;
    const float* q = &g_qkv[(size_t)dil_idx * Mm * HD];
    const float *kb, *vb;
    if (dil_idx == 0) {
        kb = &g_qkv[(size_t)3 * Mm * HD];
        vb = &g_qkv[(size_t)6 * Mm * HD];
    } else {
        kb = g_defk[dil_idx - 1];
        vb = g_defv[dil_idx - 1];
    }
    float2 q01 = *(const float2*)&q[(size_t)m * 64 + lane * 2];
    float eg[9];
    int nb[9];
    float mx = -1e30f;
    #pragma unroll
    for (int j = 0; j < 9; j++) {
        int y = h + (j / 3 - 1) * dil;
        int x = w + (j % 3 - 1) * dil;
        bool valid = ((unsigned)y < 64u) && ((unsigned)x < 64u);
        float p = 0.f;
        int base = -1;
        if (valid) {
            base = (b << 12) + (y << 6) + x;
            float2 k2 = *(const float2*)&kb[(size_t)base * 64 + lane * 2];
            p = q01.x * k2.x + q01.y * k2.y;
        }
        nb[j] = base;
        #pragma unroll
        for (int s = 16; s; s >>= 1) p += __shfl_xor_sync(0xffffffffu, p, s);
        eg[j] = p * 0.125f;
        mx = fmaxf(mx, eg[j]);
    }
    float sum = 0.f;
    #pragma unroll
    for (int j = 0; j < 9; j++) { eg[j] = expf(eg[j] - mx); sum += eg[j]; }
    float inv = 1.f / sum;
    float o0 = 0.f, o1 = 0.f;
    #pragma unroll
    for (int j = 0; j < 9; j++) {
        if (nb[j] >= 0) {
            float a = eg[j] * inv;
            float2 v2 = *(const float2*)&vb[(size_t)nb[j] * 64 + lane * 2];
            o0 += a * v2.x;
            o1 += a * v2.y;
        }
    }
    float2 o = {o0, o1};
    *(float2*)&g_attn[(size_t)m * 192 + dil_idx * 64 + lane * 2] = o;
}

// ---------------------------------------------------------------------------
extern "C" void kernel_launch(void* const* d_in, const int* in_sizes, int n_in,
                              void* d_out, int out_size)
{
    const float* x      = (const float*)d_in[0];
    const float* qkv_w  = (const float*)d_in[1];
    const float* proj_w = (const float*)d_in[2];
    const float* proj_b = (const float*)d_in[3];
    const float* off_w2 = (const float*)d_in[4];
    const float* off_b2 = (const float*)d_in[5];
    const float* def_w2 = (const float*)d_in[6];
    const float* def_b2 = (const float*)d_in[7];
    const float* off_w3 = (const float*)d_in[8];
    const float* off_b3 = (const float*)d_in[9];
    const float* def_w3 = (const float*)d_in[10];
    const float* def_b3 = (const float*)d_in[11];
    float* out = (float*)d_out;

    // 0) one-time deform-weight transpose (tiny)
    wtrans_kernel<<<288, 256>>>(def_w2, def_w3);

    // 1) qkv projection: (32768 x 192) @ (192 x 576) -> per-branch buffers
    sgemm_kernel<<<dim3(256, 9), 256>>>(x, qkv_w, nullptr, nullptr, 0);

    // 2) offset convs (dil 2, 3 merged)
    offconv_kernel<<<dim3(1024, 2), 256>>>(off_w2, off_b2, off_w3, off_b3);

    // 3) deformable conv on k and v (dil 2, 3 merged)
    deform_kernel<<<dim3(1024, 2), 256>>>(def_b2, def_b3);

    // 4) local attention, all 3 dilations
    attn_kernel<<<dim3(4096, 3), 256>>>();

    // 5) output projection + bias -> d_out
    sgemm_kernel<<<dim3(256, 3), 256>>>(nullptr, proj_w, proj_b, out, 1);
}